// round 14
// baseline (speedup 1.0000x reference)
#include <cuda_runtime.h>
#include <cuda_fp16.h>
#include <cstdint>

#define FP8_MAXF 448.0f
#define EPSF 1e-12f

// ---------------- scratch (device globals; no allocation allowed) ----------
__device__ __half   g_xq[4 * 4096 * 2048];   // quantized activations (fp16, exact integers)
__device__ __half   g_wq[2048 * 2048];       // quantized weights
__device__ float    g_wscale[2048];          // per-output-channel weight scale (pure)
__device__ unsigned g_amax_bits;             // global |x| max as uint bits (idempotent across replays)

// ---------------- fused amax + wquant ---------------------------------------
#define AMAX_BLOCKS 2048

__global__ void prep_kernel(const float* __restrict__ x, int n16,
                            const float* __restrict__ w, int K) {
    if (blockIdx.x < AMAX_BLOCKS) {
        const float4* x4 = reinterpret_cast<const float4*>(x);
        float m = 0.f;
        const int stride = AMAX_BLOCKS * blockDim.x;
        for (int i = blockIdx.x * blockDim.x + threadIdx.x; i < n16; i += stride) {
            float4 v0 = x4[i * 4 + 0];
            float4 v1 = x4[i * 4 + 1];
            float4 v2 = x4[i * 4 + 2];
            float4 v3 = x4[i * 4 + 3];
            float m0 = fmaxf(fmaxf(fabsf(v0.x), fabsf(v0.y)), fmaxf(fabsf(v0.z), fabsf(v0.w)));
            float m1 = fmaxf(fmaxf(fabsf(v1.x), fabsf(v1.y)), fmaxf(fabsf(v1.z), fabsf(v1.w)));
            float m2 = fmaxf(fmaxf(fabsf(v2.x), fabsf(v2.y)), fmaxf(fabsf(v2.z), fabsf(v2.w)));
            float m3 = fmaxf(fmaxf(fabsf(v3.x), fabsf(v3.y)), fmaxf(fabsf(v3.z), fabsf(v3.w)));
            m = fmaxf(m, fmaxf(fmaxf(m0, m1), fmaxf(m2, m3)));
        }
#pragma unroll
        for (int o = 16; o > 0; o >>= 1) m = fmaxf(m, __shfl_xor_sync(0xffffffffu, m, o));
        __shared__ float sm[8];
        int lane = threadIdx.x & 31, wi = threadIdx.x >> 5;
        if (lane == 0) sm[wi] = m;
        __syncthreads();
        if (wi == 0) {
            m = (lane < (int)(blockDim.x >> 5)) ? sm[lane] : 0.f;
#pragma unroll
            for (int o = 4; o > 0; o >>= 1) m = fmaxf(m, __shfl_xor_sync(0xffffffffu, m, o));
            if (lane == 0) atomicMax(&g_amax_bits, __float_as_uint(m));
        }
    } else {
        const int row = blockIdx.x - AMAX_BLOCKS;
        const float4* wr4 = reinterpret_cast<const float4*>(w + (size_t)row * K);
        float4 va = wr4[threadIdx.x];
        float4 vb = wr4[threadIdx.x + 256];
        float m = fmaxf(fmaxf(fabsf(va.x), fabsf(va.y)), fmaxf(fabsf(va.z), fabsf(va.w)));
        m = fmaxf(m, fmaxf(fmaxf(fabsf(vb.x), fabsf(vb.y)), fmaxf(fabsf(vb.z), fabsf(vb.w))));
#pragma unroll
        for (int o = 16; o > 0; o >>= 1) m = fmaxf(m, __shfl_xor_sync(0xffffffffu, m, o));
        __shared__ float sm[8];
        int lane = threadIdx.x & 31, wi = threadIdx.x >> 5;
        if (lane == 0) sm[wi] = m;
        __syncthreads();
        float amax = fmaxf(fmaxf(fmaxf(sm[0], sm[1]), fmaxf(sm[2], sm[3])),
                           fmaxf(fmaxf(sm[4], sm[5]), fmaxf(sm[6], sm[7])));
        float scale = fmaxf(amax / FP8_MAXF, EPSF);
        if (threadIdx.x == 0) g_wscale[row] = scale;
        float inv = 1.0f / scale;
        __half2* dq2 = reinterpret_cast<__half2*>(g_wq + (size_t)row * K);
#pragma unroll
        for (int h = 0; h < 2; h++) {
            float4 v = h ? vb : va;
            int base = (h ? (threadIdx.x + 256) : threadIdx.x) * 2;
            float q0 = rintf(fminf(fmaxf(v.x * inv, -FP8_MAXF), FP8_MAXF));
            float q1 = rintf(fminf(fmaxf(v.y * inv, -FP8_MAXF), FP8_MAXF));
            float q2 = rintf(fminf(fmaxf(v.z * inv, -FP8_MAXF), FP8_MAXF));
            float q3 = rintf(fminf(fmaxf(v.w * inv, -FP8_MAXF), FP8_MAXF));
            dq2[base + 0] = __floats2half2_rn(q0, q1);
            dq2[base + 1] = __floats2half2_rn(q2, q3);
        }
    }
}

// quantize x: 16 floats per iteration, 16B packed stores
__global__ void xquant_kernel(const float* __restrict__ x, int n16) {
    float scale = fmaxf(__uint_as_float(g_amax_bits) / FP8_MAXF, EPSF);
    float inv = 1.0f / scale;
    const float4* x4 = reinterpret_cast<const float4*>(x);
    uint4* o4 = reinterpret_cast<uint4*>(g_xq);
    const int stride = gridDim.x * blockDim.x;
    for (int i = blockIdx.x * blockDim.x + threadIdx.x; i < n16; i += stride) {
        float4 v0 = x4[i * 4 + 0];
        float4 v1 = x4[i * 4 + 1];
        float4 v2 = x4[i * 4 + 2];
        float4 v3 = x4[i * 4 + 3];
        uint32_t pk[4];
#pragma unroll
        for (int j = 0; j < 4; j += 2) {
            float4 va = (j == 0) ? v0 : v2;
            float4 vb = (j == 0) ? v1 : v3;
            float qa0 = rintf(fminf(fmaxf(va.x * inv, -FP8_MAXF), FP8_MAXF));
            float qa1 = rintf(fminf(fmaxf(va.y * inv, -FP8_MAXF), FP8_MAXF));
            float qa2 = rintf(fminf(fmaxf(va.z * inv, -FP8_MAXF), FP8_MAXF));
            float qa3 = rintf(fminf(fmaxf(va.w * inv, -FP8_MAXF), FP8_MAXF));
            float qb0 = rintf(fminf(fmaxf(vb.x * inv, -FP8_MAXF), FP8_MAXF));
            float qb1 = rintf(fminf(fmaxf(vb.y * inv, -FP8_MAXF), FP8_MAXF));
            float qb2 = rintf(fminf(fmaxf(vb.z * inv, -FP8_MAXF), FP8_MAXF));
            float qb3 = rintf(fminf(fmaxf(vb.w * inv, -FP8_MAXF), FP8_MAXF));
            __half2 h0 = __floats2half2_rn(qa0, qa1);
            __half2 h1 = __floats2half2_rn(qa2, qa3);
            __half2 h2 = __floats2half2_rn(qb0, qb1);
            __half2 h3 = __floats2half2_rn(qb2, qb3);
            pk[0] = *reinterpret_cast<uint32_t*>(&h0);
            pk[1] = *reinterpret_cast<uint32_t*>(&h1);
            pk[2] = *reinterpret_cast<uint32_t*>(&h2);
            pk[3] = *reinterpret_cast<uint32_t*>(&h3);
            o4[i * 2 + (j >> 1)] = make_uint4(pk[0], pk[1], pk[2], pk[3]);
        }
    }
}

// ---------------- GEMM: 128x128 CTA, BK=32, 5-stage fine-grained pipeline ---
// 64B rows, SW64-style swizzle (conflict-free for 16B-chunk stores and
// ldmatrix phases). 128 threads, 2x2 fat warps (64x64). 80KB smem -> 2 CTAs/SM.
// NK=64 iterations, 2 ks each: double the pipeline granularity of the
// 366.7us champion (empirical gradient: finer staging -> less tensor idle).
#define BM 128
#define BN 128
#define BKH 32                             // K chunk in halves (64 bytes/row)
#define STAGES 5
#define A_BYTES (BM * BKH * 2)             // 8192
#define B_BYTES (BN * BKH * 2)             // 8192
#define STAGE_BYTES (A_BYTES + B_BYTES)    // 16384
#define SMEM_DYN (STAGES * STAGE_BYTES)    // 81920

__device__ __forceinline__ uint32_t smem_u32(const void* p) {
    uint32_t a;
    asm("{ .reg .u64 t; cvta.to.shared.u64 t, %1; cvt.u32.u64 %0, t; }" : "=r"(a) : "l"(p));
    return a;
}

__device__ __forceinline__ void cp_async16(uint32_t saddr, const void* g) {
    asm volatile("cp.async.cg.shared.global [%0], [%1], 16;" :: "r"(saddr), "l"(g));
}

__device__ __forceinline__ void ldmx4(uint32_t r[4], uint32_t addr) {
    asm volatile("ldmatrix.sync.aligned.m8n8.x4.shared.b16 {%0,%1,%2,%3}, [%4];"
                 : "=r"(r[0]), "=r"(r[1]), "=r"(r[2]), "=r"(r[3]) : "r"(addr));
}

__device__ __forceinline__ void mma16816(float c[4], const uint32_t a[4], const uint32_t b0, const uint32_t b1) {
    asm volatile(
        "mma.sync.aligned.m16n8k16.row.col.f32.f16.f16.f32 "
        "{%0,%1,%2,%3}, {%4,%5,%6,%7}, {%8,%9}, {%0,%1,%2,%3};"
        : "+f"(c[0]), "+f"(c[1]), "+f"(c[2]), "+f"(c[3])
        : "r"(a[0]), "r"(a[1]), "r"(a[2]), "r"(a[3]), "r"(b0), "r"(b1));
}

// 64B-row swizzle: XOR chunk-index bits[5:4] with row bits (byte bits[8:7]).
// 8 consecutive rows map their 16B chunks to 8 distinct 4-bank groups.
__device__ __forceinline__ uint32_t sw64(uint32_t off) {
    return off ^ ((off >> 3) & 0x30);
}

// A: 128 rows x 64B = 512 x 16B chunks; B same. 4+4 chunks per thread.
__device__ __forceinline__ void load_stage(uint32_t sBase,
                                           const __half* __restrict__ Ag,
                                           const __half* __restrict__ Bg,
                                           int K, int kt, int tid) {
    const int kOff = kt * BKH;
#pragma unroll
    for (int i = 0; i < 4; i++) {
        int ch = tid + i * 128;
        int r = ch >> 2, c = ch & 3;
        cp_async16(sBase + sw64((uint32_t)(r * 64 + c * 16)),
                   Ag + (size_t)r * K + kOff + c * 8);
    }
#pragma unroll
    for (int i = 0; i < 4; i++) {
        int ch = tid + i * 128;
        int r = ch >> 2, c = ch & 3;
        cp_async16(sBase + A_BYTES + sw64((uint32_t)(r * 64 + c * 16)),
                   Bg + (size_t)r * K + kOff + c * 8);
    }
}

__global__ void __launch_bounds__(128, 2)
gemm_kernel(const float* __restrict__ bias, float* __restrict__ out, int M, int N, int K) {
    extern __shared__ char dsm[];
    const uint32_t dynBase = smem_u32(dsm);

    const int tid  = threadIdx.x;
    const int lane = tid & 31;
    const int warp = tid >> 5;
    const int wm = warp >> 1;   // 0..1  (64 rows)
    const int wn = warp & 1;    // 0..1  (64 cols)

    const __half* Ag = g_xq + (size_t)blockIdx.y * BM * K;
    const __half* Bg = g_wq + (size_t)blockIdx.x * BN * K;
    const int NK = K / BKH;     // 64

    float acc[4][8][4];
#pragma unroll
    for (int i = 0; i < 4; i++)
#pragma unroll
        for (int j = 0; j < 8; j++)
#pragma unroll
            for (int t = 0; t < 4; t++) acc[i][j][t] = 0.f;

    // lane-constant pre-swizzle byte offsets (64B rows)
    const uint32_t aRowOff = (uint32_t)((wm * 64 + (lane & 15)) * 64 + (lane >> 4) * 16);
    const uint32_t bRowOff = (uint32_t)((wn * 64 + (lane & 15)) * 64 + (lane >> 4) * 16);

    // prologue: fill 4 of 5 stages
#pragma unroll
    for (int p = 0; p < 4; p++) {
        load_stage(dynBase + p * STAGE_BYTES, Ag, Bg, K, p, tid);
        asm volatile("cp.async.commit_group;");
    }

    for (int kt = 0; kt < NK; kt++) {
        // wait for stage kt: keep up to 3 newer groups in flight
        if (kt + 3 < NK)      asm volatile("cp.async.wait_group 3;");
        else if (kt + 2 < NK) asm volatile("cp.async.wait_group 2;");
        else if (kt + 1 < NK) asm volatile("cp.async.wait_group 1;");
        else                  asm volatile("cp.async.wait_group 0;");
        __syncthreads();

        const int s = kt % STAGES;
        const uint32_t aBase = dynBase + s * STAGE_BYTES;
        const uint32_t bBase = aBase + A_BYTES;

        if (kt + 4 < NK) {
            load_stage(dynBase + ((kt + 4) % STAGES) * STAGE_BYTES, Ag, Bg, K, kt + 4, tid);
            asm volatile("cp.async.commit_group;");
        }

#pragma unroll
        for (int ks = 0; ks < 2; ks++) {
            const uint32_t kcol = (uint32_t)(ks * 32);
            uint32_t a[4][4], b[4][4];
#pragma unroll
            for (int mf = 0; mf < 4; mf++)
                ldmx4(a[mf], aBase + sw64(aRowOff + (uint32_t)(mf * 16 * 64) + kcol));
#pragma unroll
            for (int p = 0; p < 4; p++)
                ldmx4(b[p], bBase + sw64(bRowOff + (uint32_t)(p * 16 * 64) + kcol));
#pragma unroll
            for (int mf = 0; mf < 4; mf++)
#pragma unroll
                for (int p = 0; p < 4; p++) {
                    mma16816(acc[mf][p * 2 + 0], a[mf], b[p][0], b[p][2]);
                    mma16816(acc[mf][p * 2 + 1], a[mf], b[p][1], b[p][3]);
                }
        }
    }

    // epilogue: out = acc * (input_scale * wscale[n]) + bias[n]
    const float is = fmaxf(__uint_as_float(g_amax_bits) / FP8_MAXF, EPSF);
    const int rowBase = blockIdx.y * BM + wm * 64 + (lane >> 2);
    const int colBase = blockIdx.x * BN + wn * 64 + (lane & 3) * 2;
#pragma unroll
    for (int nf = 0; nf < 8; nf++) {
        int col = colBase + nf * 8;
        float s0 = is * __ldg(&g_wscale[col]);
        float s1 = is * __ldg(&g_wscale[col + 1]);
        float b0 = __ldg(&bias[col]);
        float b1 = __ldg(&bias[col + 1]);
#pragma unroll
        for (int mf = 0; mf < 4; mf++) {
            int r0 = rowBase + mf * 16;
            float2 v0 = make_float2(fmaf(acc[mf][nf][0], s0, b0), fmaf(acc[mf][nf][1], s1, b1));
            float2 v1 = make_float2(fmaf(acc[mf][nf][2], s0, b0), fmaf(acc[mf][nf][3], s1, b1));
            *(float2*)&out[(size_t)r0 * N + col] = v0;
            *(float2*)&out[(size_t)(r0 + 8) * N + col] = v1;
        }
    }
}

// ---------------- launch ----------------------------------------------------
extern "C" void kernel_launch(void* const* d_in, const int* in_sizes, int n_in,
                              void* d_out, int out_size) {
    const float* x    = (const float*)d_in[0];
    const float* w    = (const float*)d_in[1];
    const float* bias = (const float*)d_in[2];
    float* out = (float*)d_out;

    const int N = in_sizes[2];                        // 2048
    const int K = in_sizes[1] / N;                    // 2048
    const int M = (int)((long long)in_sizes[0] / K);  // 16384
    const int n16 = in_sizes[0] / 16;

    prep_kernel<<<AMAX_BLOCKS + N, 256>>>(x, n16, w, K);
    xquant_kernel<<<2048, 256>>>(x, n16);

    cudaFuncSetAttribute(gemm_kernel, cudaFuncAttributeMaxDynamicSharedMemorySize, SMEM_DYN);
    dim3 grid(N / BN, M / BM);
    gemm_kernel<<<grid, 128, SMEM_DYN>>>(bias, out, M, N, K);
}

// round 15
// speedup vs baseline: 1.1041x; 1.1041x over previous
#include <cuda_runtime.h>
#include <cuda_fp16.h>
#include <cstdint>

#define FP8_MAXF 448.0f
#define EPSF 1e-12f

// ---------------- scratch (device globals; no allocation allowed) ----------
__device__ __half   g_xq[4 * 4096 * 2048];   // quantized activations (fp16, exact integers)
__device__ __half   g_wq[2048 * 2048];       // quantized weights
__device__ float    g_wscale[2048];          // per-output-channel weight scale (pure)
__device__ unsigned g_amax_bits;             // global |x| max as uint bits (idempotent across replays)

// ---------------- fused amax + wquant ---------------------------------------
#define AMAX_BLOCKS 2048

__global__ void prep_kernel(const float* __restrict__ x, int n16,
                            const float* __restrict__ w, int K) {
    if (blockIdx.x < AMAX_BLOCKS) {
        const float4* x4 = reinterpret_cast<const float4*>(x);
        float m = 0.f;
        const int stride = AMAX_BLOCKS * blockDim.x;
        for (int i = blockIdx.x * blockDim.x + threadIdx.x; i < n16; i += stride) {
            float4 v0 = x4[i * 4 + 0];
            float4 v1 = x4[i * 4 + 1];
            float4 v2 = x4[i * 4 + 2];
            float4 v3 = x4[i * 4 + 3];
            float m0 = fmaxf(fmaxf(fabsf(v0.x), fabsf(v0.y)), fmaxf(fabsf(v0.z), fabsf(v0.w)));
            float m1 = fmaxf(fmaxf(fabsf(v1.x), fabsf(v1.y)), fmaxf(fabsf(v1.z), fabsf(v1.w)));
            float m2 = fmaxf(fmaxf(fabsf(v2.x), fabsf(v2.y)), fmaxf(fabsf(v2.z), fabsf(v2.w)));
            float m3 = fmaxf(fmaxf(fabsf(v3.x), fabsf(v3.y)), fmaxf(fabsf(v3.z), fabsf(v3.w)));
            m = fmaxf(m, fmaxf(fmaxf(m0, m1), fmaxf(m2, m3)));
        }
#pragma unroll
        for (int o = 16; o > 0; o >>= 1) m = fmaxf(m, __shfl_xor_sync(0xffffffffu, m, o));
        __shared__ float sm[8];
        int lane = threadIdx.x & 31, wi = threadIdx.x >> 5;
        if (lane == 0) sm[wi] = m;
        __syncthreads();
        if (wi == 0) {
            m = (lane < (int)(blockDim.x >> 5)) ? sm[lane] : 0.f;
#pragma unroll
            for (int o = 4; o > 0; o >>= 1) m = fmaxf(m, __shfl_xor_sync(0xffffffffu, m, o));
            if (lane == 0) atomicMax(&g_amax_bits, __float_as_uint(m));
        }
    } else {
        const int row = blockIdx.x - AMAX_BLOCKS;
        const float4* wr4 = reinterpret_cast<const float4*>(w + (size_t)row * K);
        float4 va = wr4[threadIdx.x];
        float4 vb = wr4[threadIdx.x + 256];
        float m = fmaxf(fmaxf(fabsf(va.x), fabsf(va.y)), fmaxf(fabsf(va.z), fabsf(va.w)));
        m = fmaxf(m, fmaxf(fmaxf(fabsf(vb.x), fabsf(vb.y)), fmaxf(fabsf(vb.z), fabsf(vb.w))));
#pragma unroll
        for (int o = 16; o > 0; o >>= 1) m = fmaxf(m, __shfl_xor_sync(0xffffffffu, m, o));
        __shared__ float sm[8];
        int lane = threadIdx.x & 31, wi = threadIdx.x >> 5;
        if (lane == 0) sm[wi] = m;
        __syncthreads();
        float amax = fmaxf(fmaxf(fmaxf(sm[0], sm[1]), fmaxf(sm[2], sm[3])),
                           fmaxf(fmaxf(sm[4], sm[5]), fmaxf(sm[6], sm[7])));
        float scale = fmaxf(amax / FP8_MAXF, EPSF);
        if (threadIdx.x == 0) g_wscale[row] = scale;
        float inv = 1.0f / scale;
        __half2* dq2 = reinterpret_cast<__half2*>(g_wq + (size_t)row * K);
#pragma unroll
        for (int h = 0; h < 2; h++) {
            float4 v = h ? vb : va;
            int base = (h ? (threadIdx.x + 256) : threadIdx.x) * 2;
            float q0 = rintf(fminf(fmaxf(v.x * inv, -FP8_MAXF), FP8_MAXF));
            float q1 = rintf(fminf(fmaxf(v.y * inv, -FP8_MAXF), FP8_MAXF));
            float q2 = rintf(fminf(fmaxf(v.z * inv, -FP8_MAXF), FP8_MAXF));
            float q3 = rintf(fminf(fmaxf(v.w * inv, -FP8_MAXF), FP8_MAXF));
            dq2[base + 0] = __floats2half2_rn(q0, q1);
            dq2[base + 1] = __floats2half2_rn(q2, q3);
        }
    }
}

// quantize x: 16 floats (4 independent float4 loads) per iteration, 16B stores
__global__ void xquant_kernel(const float* __restrict__ x, int n16) {
    float scale = fmaxf(__uint_as_float(g_amax_bits) / FP8_MAXF, EPSF);
    float inv = 1.0f / scale;
    const float4* x4 = reinterpret_cast<const float4*>(x);
    uint4* o4 = reinterpret_cast<uint4*>(g_xq);
    const int stride = gridDim.x * blockDim.x;
    for (int i = blockIdx.x * blockDim.x + threadIdx.x; i < n16; i += stride) {
        float4 v0 = x4[i * 4 + 0];
        float4 v1 = x4[i * 4 + 1];
        float4 v2 = x4[i * 4 + 2];
        float4 v3 = x4[i * 4 + 3];
        uint32_t pk[4];
#pragma unroll
        for (int j = 0; j < 4; j += 2) {
            float4 va = (j == 0) ? v0 : v2;
            float4 vb = (j == 0) ? v1 : v3;
            float qa0 = rintf(fminf(fmaxf(va.x * inv, -FP8_MAXF), FP8_MAXF));
            float qa1 = rintf(fminf(fmaxf(va.y * inv, -FP8_MAXF), FP8_MAXF));
            float qa2 = rintf(fminf(fmaxf(va.z * inv, -FP8_MAXF), FP8_MAXF));
            float qa3 = rintf(fminf(fmaxf(va.w * inv, -FP8_MAXF), FP8_MAXF));
            float qb0 = rintf(fminf(fmaxf(vb.x * inv, -FP8_MAXF), FP8_MAXF));
            float qb1 = rintf(fminf(fmaxf(vb.y * inv, -FP8_MAXF), FP8_MAXF));
            float qb2 = rintf(fminf(fmaxf(vb.z * inv, -FP8_MAXF), FP8_MAXF));
            float qb3 = rintf(fminf(fmaxf(vb.w * inv, -FP8_MAXF), FP8_MAXF));
            __half2 h0 = __floats2half2_rn(qa0, qa1);
            __half2 h1 = __floats2half2_rn(qa2, qa3);
            __half2 h2 = __floats2half2_rn(qb0, qb1);
            __half2 h3 = __floats2half2_rn(qb2, qb3);
            pk[0] = *reinterpret_cast<uint32_t*>(&h0);
            pk[1] = *reinterpret_cast<uint32_t*>(&h1);
            pk[2] = *reinterpret_cast<uint32_t*>(&h2);
            pk[3] = *reinterpret_cast<uint32_t*>(&h3);
            o4[i * 2 + (j >> 1)] = make_uint4(pk[0], pk[1], pk[2], pk[3]);
        }
    }
}

// ---------------- GEMM: R12 champion config ---------------------------------
// CTA 128x128, 2x2 fat warps (64x64), BK=64 halves (128B rows, SW128).
// 128 threads, 3-stage cp.async, 96KB smem -> 2 CTAs/SM.
// Epilogue uses evict-first (.cs) stores: output is write-once, keep B/A in L2.
#define BM 128
#define BN 128
#define BKH 64
#define STAGES 3
#define A_BYTES (BM * BKH * 2)            // 16384
#define B_BYTES (BN * BKH * 2)            // 16384
#define STAGE_BYTES (A_BYTES + B_BYTES)   // 32768
#define SMEM_DYN (STAGES * STAGE_BYTES)   // 98304

__device__ __forceinline__ uint32_t smem_u32(const void* p) {
    uint32_t a;
    asm("{ .reg .u64 t; cvta.to.shared.u64 t, %1; cvt.u32.u64 %0, t; }" : "=r"(a) : "l"(p));
    return a;
}

__device__ __forceinline__ void cp_async16(uint32_t saddr, const void* g) {
    asm volatile("cp.async.cg.shared.global [%0], [%1], 16;" :: "r"(saddr), "l"(g));
}

__device__ __forceinline__ void ldmx4(uint32_t r[4], uint32_t addr) {
    asm volatile("ldmatrix.sync.aligned.m8n8.x4.shared.b16 {%0,%1,%2,%3}, [%4];"
                 : "=r"(r[0]), "=r"(r[1]), "=r"(r[2]), "=r"(r[3]) : "r"(addr));
}

__device__ __forceinline__ void mma16816(float c[4], const uint32_t a[4], const uint32_t b0, const uint32_t b1) {
    asm volatile(
        "mma.sync.aligned.m16n8k16.row.col.f32.f16.f16.f32 "
        "{%0,%1,%2,%3}, {%4,%5,%6,%7}, {%8,%9}, {%0,%1,%2,%3};"
        : "+f"(c[0]), "+f"(c[1]), "+f"(c[2]), "+f"(c[3])
        : "r"(a[0]), "r"(a[1]), "r"(a[2]), "r"(a[3]), "r"(b0), "r"(b1));
}

__device__ __forceinline__ uint32_t sw128(uint32_t off) {
    return off ^ ((off >> 3) & 0x70);
}

__device__ __forceinline__ void load_stage(uint32_t sBase,
                                           const __half* __restrict__ Ag,
                                           const __half* __restrict__ Bg,
                                           int K, int kt, int tid) {
    const int kOff = kt * BKH;
#pragma unroll
    for (int i = 0; i < 8; i++) {          // A: 1024 x 16B chunks / 128 threads
        int ch = tid + i * 128;
        int r = ch >> 3, c = ch & 7;
        cp_async16(sBase + sw128((uint32_t)(r * 128 + c * 16)),
                   Ag + (size_t)r * K + kOff + c * 8);
    }
#pragma unroll
    for (int i = 0; i < 8; i++) {          // B: 1024 x 16B chunks / 128 threads
        int ch = tid + i * 128;
        int r = ch >> 3, c = ch & 7;
        cp_async16(sBase + A_BYTES + sw128((uint32_t)(r * 128 + c * 16)),
                   Bg + (size_t)r * K + kOff + c * 8);
    }
}

__global__ void __launch_bounds__(128, 2)
gemm_kernel(const float* __restrict__ bias, float* __restrict__ out, int M, int N, int K) {
    extern __shared__ char dsm[];
    const uint32_t dynBase = smem_u32(dsm);

    const int tid  = threadIdx.x;
    const int lane = tid & 31;
    const int warp = tid >> 5;
    const int wm = warp >> 1;   // 0..1  (64 rows)
    const int wn = warp & 1;    // 0..1  (64 cols)

    const __half* Ag = g_xq + (size_t)blockIdx.y * BM * K;
    const __half* Bg = g_wq + (size_t)blockIdx.x * BN * K;
    const int NK = K / BKH;     // 32

    float acc[4][8][4];
#pragma unroll
    for (int i = 0; i < 4; i++)
#pragma unroll
        for (int j = 0; j < 8; j++)
#pragma unroll
            for (int t = 0; t < 4; t++) acc[i][j][t] = 0.f;

    const uint32_t aRowOff = (uint32_t)((wm * 64 + (lane & 15)) * 128 + (lane >> 4) * 16);
    const uint32_t bRowOff = (uint32_t)((wn * 64 + (lane & 15)) * 128 + (lane >> 4) * 16);

    load_stage(dynBase, Ag, Bg, K, 0, tid);
    asm volatile("cp.async.commit_group;");
    load_stage(dynBase + STAGE_BYTES, Ag, Bg, K, 1, tid);
    asm volatile("cp.async.commit_group;");

    for (int kt = 0; kt < NK; kt++) {
        if (kt + 1 < NK) asm volatile("cp.async.wait_group 1;");
        else             asm volatile("cp.async.wait_group 0;");
        __syncthreads();

        const int s = kt % STAGES;
        const uint32_t aBase = dynBase + s * STAGE_BYTES;
        const uint32_t bBase = aBase + A_BYTES;

        if (kt + 2 < NK) {
            load_stage(dynBase + ((kt + 2) % STAGES) * STAGE_BYTES, Ag, Bg, K, kt + 2, tid);
            asm volatile("cp.async.commit_group;");
        }

#pragma unroll
        for (int ks = 0; ks < 4; ks++) {
            const uint32_t kcol = (uint32_t)(ks * 32);
            uint32_t a[4][4], b[4][4];
#pragma unroll
            for (int mf = 0; mf < 4; mf++)
                ldmx4(a[mf], aBase + sw128(aRowOff + (uint32_t)(mf * 16 * 128) + kcol));
#pragma unroll
            for (int p = 0; p < 4; p++)
                ldmx4(b[p], bBase + sw128(bRowOff + (uint32_t)(p * 16 * 128) + kcol));
#pragma unroll
            for (int mf = 0; mf < 4; mf++)
#pragma unroll
                for (int p = 0; p < 4; p++) {
                    mma16816(acc[mf][p * 2 + 0], a[mf], b[p][0], b[p][2]);
                    mma16816(acc[mf][p * 2 + 1], a[mf], b[p][1], b[p][3]);
                }
        }
    }

    // epilogue: out = acc * (input_scale * wscale[n]) + bias[n]
    // evict-first stores: out is write-once, keep GEMM operands resident in L2
    const float is = fmaxf(__uint_as_float(g_amax_bits) / FP8_MAXF, EPSF);
    const int rowBase = blockIdx.y * BM + wm * 64 + (lane >> 2);
    const int colBase = blockIdx.x * BN + wn * 64 + (lane & 3) * 2;
#pragma unroll
    for (int nf = 0; nf < 8; nf++) {
        int col = colBase + nf * 8;
        float s0 = is * __ldg(&g_wscale[col]);
        float s1 = is * __ldg(&g_wscale[col + 1]);
        float b0 = __ldg(&bias[col]);
        float b1 = __ldg(&bias[col + 1]);
#pragma unroll
        for (int mf = 0; mf < 4; mf++) {
            int r0 = rowBase + mf * 16;
            float2 v0 = make_float2(fmaf(acc[mf][nf][0], s0, b0), fmaf(acc[mf][nf][1], s1, b1));
            float2 v1 = make_float2(fmaf(acc[mf][nf][2], s0, b0), fmaf(acc[mf][nf][3], s1, b1));
            __stcs(reinterpret_cast<float2*>(&out[(size_t)r0 * N + col]), v0);
            __stcs(reinterpret_cast<float2*>(&out[(size_t)(r0 + 8) * N + col]), v1);
        }
    }
}

// ---------------- launch ----------------------------------------------------
extern "C" void kernel_launch(void* const* d_in, const int* in_sizes, int n_in,
                              void* d_out, int out_size) {
    const float* x    = (const float*)d_in[0];
    const float* w    = (const float*)d_in[1];
    const float* bias = (const float*)d_in[2];
    float* out = (float*)d_out;

    const int N = in_sizes[2];                        // 2048
    const int K = in_sizes[1] / N;                    // 2048
    const int M = (int)((long long)in_sizes[0] / K);  // 16384
    const int n16 = in_sizes[0] / 16;

    prep_kernel<<<AMAX_BLOCKS + N, 256>>>(x, n16, w, K);
    xquant_kernel<<<2048, 256>>>(x, n16);

    cudaFuncSetAttribute(gemm_kernel, cudaFuncAttributeMaxDynamicSharedMemorySize, SMEM_DYN);
    dim3 grid(N / BN, M / BM);
    gemm_kernel<<<grid, 128, SMEM_DYN>>>(bias, out, M, N, K);
}

// round 17
// speedup vs baseline: 1.1076x; 1.0032x over previous
#include <cuda_runtime.h>
#include <cuda_fp16.h>
#include <cstdint>

#define FP8_MAXF 448.0f
#define EPSF 1e-12f

// ---------------- scratch (device globals; no allocation allowed) ----------
__device__ __half   g_xq[4 * 4096 * 2048];   // quantized activations (fp16, exact integers)
__device__ __half   g_wq[2048 * 2048];       // quantized weights
__device__ float    g_wscale[2048];          // per-output-channel weight scale (pure)
__device__ unsigned g_amax_bits;             // global |x| max as uint bits (idempotent across replays)

// ---------------- fused amax + wquant ---------------------------------------
#define AMAX_BLOCKS 2048

__global__ void prep_kernel(const float* __restrict__ x, int n16,
                            const float* __restrict__ w, int K) {
    if (blockIdx.x < AMAX_BLOCKS) {
        const float4* x4 = reinterpret_cast<const float4*>(x);
        float m = 0.f;
        const int stride = AMAX_BLOCKS * blockDim.x;
        for (int i = blockIdx.x * blockDim.x + threadIdx.x; i < n16; i += stride) {
            float4 v0 = x4[i * 4 + 0];
            float4 v1 = x4[i * 4 + 1];
            float4 v2 = x4[i * 4 + 2];
            float4 v3 = x4[i * 4 + 3];
            float m0 = fmaxf(fmaxf(fabsf(v0.x), fabsf(v0.y)), fmaxf(fabsf(v0.z), fabsf(v0.w)));
            float m1 = fmaxf(fmaxf(fabsf(v1.x), fabsf(v1.y)), fmaxf(fabsf(v1.z), fabsf(v1.w)));
            float m2 = fmaxf(fmaxf(fabsf(v2.x), fabsf(v2.y)), fmaxf(fabsf(v2.z), fabsf(v2.w)));
            float m3 = fmaxf(fmaxf(fabsf(v3.x), fabsf(v3.y)), fmaxf(fabsf(v3.z), fabsf(v3.w)));
            m = fmaxf(m, fmaxf(fmaxf(m0, m1), fmaxf(m2, m3)));
        }
#pragma unroll
        for (int o = 16; o > 0; o >>= 1) m = fmaxf(m, __shfl_xor_sync(0xffffffffu, m, o));
        __shared__ float sm[8];
        int lane = threadIdx.x & 31, wi = threadIdx.x >> 5;
        if (lane == 0) sm[wi] = m;
        __syncthreads();
        if (wi == 0) {
            m = (lane < (int)(blockDim.x >> 5)) ? sm[lane] : 0.f;
#pragma unroll
            for (int o = 4; o > 0; o >>= 1) m = fmaxf(m, __shfl_xor_sync(0xffffffffu, m, o));
            if (lane == 0) atomicMax(&g_amax_bits, __float_as_uint(m));
        }
    } else {
        const int row = blockIdx.x - AMAX_BLOCKS;
        const float4* wr4 = reinterpret_cast<const float4*>(w + (size_t)row * K);
        float4 va = wr4[threadIdx.x];
        float4 vb = wr4[threadIdx.x + 256];
        float m = fmaxf(fmaxf(fabsf(va.x), fabsf(va.y)), fmaxf(fabsf(va.z), fabsf(va.w)));
        m = fmaxf(m, fmaxf(fmaxf(fabsf(vb.x), fabsf(vb.y)), fmaxf(fabsf(vb.z), fabsf(vb.w))));
#pragma unroll
        for (int o = 16; o > 0; o >>= 1) m = fmaxf(m, __shfl_xor_sync(0xffffffffu, m, o));
        __shared__ float sm[8];
        int lane = threadIdx.x & 31, wi = threadIdx.x >> 5;
        if (lane == 0) sm[wi] = m;
        __syncthreads();
        float amax = fmaxf(fmaxf(fmaxf(sm[0], sm[1]), fmaxf(sm[2], sm[3])),
                           fmaxf(fmaxf(sm[4], sm[5]), fmaxf(sm[6], sm[7])));
        float scale = fmaxf(amax / FP8_MAXF, EPSF);
        if (threadIdx.x == 0) g_wscale[row] = scale;
        float inv = 1.0f / scale;
        __half2* dq2 = reinterpret_cast<__half2*>(g_wq + (size_t)row * K);
#pragma unroll
        for (int h = 0; h < 2; h++) {
            float4 v = h ? vb : va;
            int base = (h ? (threadIdx.x + 256) : threadIdx.x) * 2;
            float q0 = rintf(fminf(fmaxf(v.x * inv, -FP8_MAXF), FP8_MAXF));
            float q1 = rintf(fminf(fmaxf(v.y * inv, -FP8_MAXF), FP8_MAXF));
            float q2 = rintf(fminf(fmaxf(v.z * inv, -FP8_MAXF), FP8_MAXF));
            float q3 = rintf(fminf(fmaxf(v.w * inv, -FP8_MAXF), FP8_MAXF));
            dq2[base + 0] = __floats2half2_rn(q0, q1);
            dq2[base + 1] = __floats2half2_rn(q2, q3);
        }
    }
}

// quantize x: last use of x -> streaming loads (__ldcs); 16B packed stores
__global__ void xquant_kernel(const float* __restrict__ x, int n16) {
    float scale = fmaxf(__uint_as_float(g_amax_bits) / FP8_MAXF, EPSF);
    float inv = 1.0f / scale;
    const float4* x4 = reinterpret_cast<const float4*>(x);
    uint4* o4 = reinterpret_cast<uint4*>(g_xq);
    const int stride = gridDim.x * blockDim.x;
    for (int i = blockIdx.x * blockDim.x + threadIdx.x; i < n16; i += stride) {
        float4 v0 = __ldcs(&x4[i * 4 + 0]);
        float4 v1 = __ldcs(&x4[i * 4 + 1]);
        float4 v2 = __ldcs(&x4[i * 4 + 2]);
        float4 v3 = __ldcs(&x4[i * 4 + 3]);
        uint32_t pk[4];
#pragma unroll
        for (int j = 0; j < 4; j += 2) {
            float4 va = (j == 0) ? v0 : v2;
            float4 vb = (j == 0) ? v1 : v3;
            float qa0 = rintf(fminf(fmaxf(va.x * inv, -FP8_MAXF), FP8_MAXF));
            float qa1 = rintf(fminf(fmaxf(va.y * inv, -FP8_MAXF), FP8_MAXF));
            float qa2 = rintf(fminf(fmaxf(va.z * inv, -FP8_MAXF), FP8_MAXF));
            float qa3 = rintf(fminf(fmaxf(va.w * inv, -FP8_MAXF), FP8_MAXF));
            float qb0 = rintf(fminf(fmaxf(vb.x * inv, -FP8_MAXF), FP8_MAXF));
            float qb1 = rintf(fminf(fmaxf(vb.y * inv, -FP8_MAXF), FP8_MAXF));
            float qb2 = rintf(fminf(fmaxf(vb.z * inv, -FP8_MAXF), FP8_MAXF));
            float qb3 = rintf(fminf(fmaxf(vb.w * inv, -FP8_MAXF), FP8_MAXF));
            __half2 h0 = __floats2half2_rn(qa0, qa1);
            __half2 h1 = __floats2half2_rn(qa2, qa3);
            __half2 h2 = __floats2half2_rn(qb0, qb1);
            __half2 h3 = __floats2half2_rn(qb2, qb3);
            pk[0] = *reinterpret_cast<uint32_t*>(&h0);
            pk[1] = *reinterpret_cast<uint32_t*>(&h1);
            pk[2] = *reinterpret_cast<uint32_t*>(&h2);
            pk[3] = *reinterpret_cast<uint32_t*>(&h3);
            o4[i * 2 + (j >> 1)] = make_uint4(pk[0], pk[1], pk[2], pk[3]);
        }
    }
}

// ---------------- GEMM: R15 champion config (424.3us) -----------------------
// CTA 128x128, 2x2 fat warps (64x64), BK=64 halves (128B rows, SW128).
// 128 threads, 3-stage cp.async, 96KB smem -> 2 CTAs/SM. __stcs epilogue
// (evict-first output stores keep B/A operand panels resident in L2).
#define BM 128
#define BN 128
#define BKH 64
#define STAGES 3
#define A_BYTES (BM * BKH * 2)            // 16384
#define B_BYTES (BN * BKH * 2)            // 16384
#define STAGE_BYTES (A_BYTES + B_BYTES)   // 32768
#define SMEM_DYN (STAGES * STAGE_BYTES)   // 98304

__device__ __forceinline__ uint32_t smem_u32(const void* p) {
    uint32_t a;
    asm("{ .reg .u64 t; cvta.to.shared.u64 t, %1; cvt.u32.u64 %0, t; }" : "=r"(a) : "l"(p));
    return a;
}

__device__ __forceinline__ void cp_async16(uint32_t saddr, const void* g) {
    asm volatile("cp.async.cg.shared.global [%0], [%1], 16;" :: "r"(saddr), "l"(g));
}

__device__ __forceinline__ void ldmx4(uint32_t r[4], uint32_t addr) {
    asm volatile("ldmatrix.sync.aligned.m8n8.x4.shared.b16 {%0,%1,%2,%3}, [%4];"
                 : "=r"(r[0]), "=r"(r[1]), "=r"(r[2]), "=r"(r[3]) : "r"(addr));
}

__device__ __forceinline__ void mma16816(float c[4], const uint32_t a[4], const uint32_t b0, const uint32_t b1) {
    asm volatile(
        "mma.sync.aligned.m16n8k16.row.col.f32.f16.f16.f32 "
        "{%0,%1,%2,%3}, {%4,%5,%6,%7}, {%8,%9}, {%0,%1,%2,%3};"
        : "+f"(c[0]), "+f"(c[1]), "+f"(c[2]), "+f"(c[3])
        : "r"(a[0]), "r"(a[1]), "r"(a[2]), "r"(a[3]), "r"(b0), "r"(b1));
}

__device__ __forceinline__ uint32_t sw128(uint32_t off) {
    return off ^ ((off >> 3) & 0x70);
}

__device__ __forceinline__ void load_stage(uint32_t sBase,
                                           const __half* __restrict__ Ag,
                                           const __half* __restrict__ Bg,
                                           int K, int kt, int tid) {
    const int kOff = kt * BKH;
#pragma unroll
    for (int i = 0; i < 8; i++) {          // A: 1024 x 16B chunks / 128 threads
        int ch = tid + i * 128;
        int r = ch >> 3, c = ch & 7;
        cp_async16(sBase + sw128((uint32_t)(r * 128 + c * 16)),
                   Ag + (size_t)r * K + kOff + c * 8);
    }
#pragma unroll
    for (int i = 0; i < 8; i++) {          // B: 1024 x 16B chunks / 128 threads
        int ch = tid + i * 128;
        int r = ch >> 3, c = ch & 7;
        cp_async16(sBase + A_BYTES + sw128((uint32_t)(r * 128 + c * 16)),
                   Bg + (size_t)r * K + kOff + c * 8);
    }
}

__global__ void __launch_bounds__(128, 2)
gemm_kernel(const float* __restrict__ bias, float* __restrict__ out, int M, int N, int K) {
    extern __shared__ char dsm[];
    const uint32_t dynBase = smem_u32(dsm);

    const int tid  = threadIdx.x;
    const int lane = tid & 31;
    const int warp = tid >> 5;
    const int wm = warp >> 1;   // 0..1  (64 rows)
    const int wn = warp & 1;    // 0..1  (64 cols)

    const __half* Ag = g_xq + (size_t)blockIdx.y * BM * K;
    const __half* Bg = g_wq + (size_t)blockIdx.x * BN * K;
    const int NK = K / BKH;     // 32

    float acc[4][8][4];
#pragma unroll
    for (int i = 0; i < 4; i++)
#pragma unroll
        for (int j = 0; j < 8; j++)
#pragma unroll
            for (int t = 0; t < 4; t++) acc[i][j][t] = 0.f;

    const uint32_t aRowOff = (uint32_t)((wm * 64 + (lane & 15)) * 128 + (lane >> 4) * 16);
    const uint32_t bRowOff = (uint32_t)((wn * 64 + (lane & 15)) * 128 + (lane >> 4) * 16);

    load_stage(dynBase, Ag, Bg, K, 0, tid);
    asm volatile("cp.async.commit_group;");
    load_stage(dynBase + STAGE_BYTES, Ag, Bg, K, 1, tid);
    asm volatile("cp.async.commit_group;");

    for (int kt = 0; kt < NK; kt++) {
        if (kt + 1 < NK) asm volatile("cp.async.wait_group 1;");
        else             asm volatile("cp.async.wait_group 0;");
        __syncthreads();

        const int s = kt % STAGES;
        const uint32_t aBase = dynBase + s * STAGE_BYTES;
        const uint32_t bBase = aBase + A_BYTES;

        if (kt + 2 < NK) {
            load_stage(dynBase + ((kt + 2) % STAGES) * STAGE_BYTES, Ag, Bg, K, kt + 2, tid);
            asm volatile("cp.async.commit_group;");
        }

#pragma unroll
        for (int ks = 0; ks < 4; ks++) {
            const uint32_t kcol = (uint32_t)(ks * 32);
            uint32_t a[4][4], b[4][4];
#pragma unroll
            for (int mf = 0; mf < 4; mf++)
                ldmx4(a[mf], aBase + sw128(aRowOff + (uint32_t)(mf * 16 * 128) + kcol));
#pragma unroll
            for (int p = 0; p < 4; p++)
                ldmx4(b[p], bBase + sw128(bRowOff + (uint32_t)(p * 16 * 128) + kcol));
#pragma unroll
            for (int mf = 0; mf < 4; mf++)
#pragma unroll
                for (int p = 0; p < 4; p++) {
                    mma16816(acc[mf][p * 2 + 0], a[mf], b[p][0], b[p][2]);
                    mma16816(acc[mf][p * 2 + 1], a[mf], b[p][1], b[p][3]);
                }
        }
    }

    // epilogue: out = acc * (input_scale * wscale[n]) + bias[n]
    // evict-first stores: out is write-once, keep GEMM operands resident in L2
    const float is = fmaxf(__uint_as_float(g_amax_bits) / FP8_MAXF, EPSF);
    const int rowBase = blockIdx.y * BM + wm * 64 + (lane >> 2);
    const int colBase = blockIdx.x * BN + wn * 64 + (lane & 3) * 2;
#pragma unroll
    for (int nf = 0; nf < 8; nf++) {
        int col = colBase + nf * 8;
        float s0 = is * __ldg(&g_wscale[col]);
        float s1 = is * __ldg(&g_wscale[col + 1]);
        float b0 = __ldg(&bias[col]);
        float b1 = __ldg(&bias[col + 1]);
#pragma unroll
        for (int mf = 0; mf < 4; mf++) {
            int r0 = rowBase + mf * 16;
            float2 v0 = make_float2(fmaf(acc[mf][nf][0], s0, b0), fmaf(acc[mf][nf][1], s1, b1));
            float2 v1 = make_float2(fmaf(acc[mf][nf][2], s0, b0), fmaf(acc[mf][nf][3], s1, b1));
            __stcs(reinterpret_cast<float2*>(&out[(size_t)r0 * N + col]), v0);
            __stcs(reinterpret_cast<float2*>(&out[(size_t)(r0 + 8) * N + col]), v1);
        }
    }
}

// ---------------- launch ----------------------------------------------------
extern "C" void kernel_launch(void* const* d_in, const int* in_sizes, int n_in,
                              void* d_out, int out_size) {
    const float* x    = (const float*)d_in[0];
    const float* w    = (const float*)d_in[1];
    const float* bias = (const float*)d_in[2];
    float* out = (float*)d_out;

    const int N = in_sizes[2];                        // 2048
    const int K = in_sizes[1] / N;                    // 2048
    const int M = (int)((long long)in_sizes[0] / K);  // 16384
    const int n16 = in_sizes[0] / 16;

    prep_kernel<<<AMAX_BLOCKS + N, 256>>>(x, n16, w, K);
    xquant_kernel<<<2048, 256>>>(x, n16);

    cudaFuncSetAttribute(gemm_kernel, cudaFuncAttributeMaxDynamicSharedMemorySize, SMEM_DYN);
    dim3 grid(N / BN, M / BM);
    gemm_kernel<<<grid, 128, SMEM_DYN>>>(bias, out, M, N, K);
}